// round 3
// baseline (speedup 1.0000x reference)
#include <cuda_runtime.h>
#include <cuda_bf16.h>
#include <math.h>

// Problem constants
#define B_  2
#define N_  2048
#define C_  1024
#define R_  64
#define H_  16
#define DH_ 64
#define M_  (B_ * N_)          // 4096 rows
#define QKV3_ (3 * C_)         // 3072

// Scratch (device globals: allocation-free)
__device__ float g_h1[M_ * R_];          // 1 MB
__device__ float g_qkv[M_ * QKV3_];      // 48 MB
__device__ float g_attn[M_ * C_];        // 16 MB
__device__ float g_h2[M_ * R_];          // 1 MB

__device__ __forceinline__ float gelu_exact(float x) {
    return 0.5f * x * (1.0f + erff(x * 0.70710678118654752f));
}

// ---------------------------------------------------------------------------
// GEMM "rank": [M,1024] @ [1024,64] (+bias) (gelu) -> [M,64]
// Block: 32 rows x 64 cols, 256 threads (16x16), 2x4 per thread, K-tiles of 32
// ---------------------------------------------------------------------------
__global__ void gemm_rank_kernel(const float* __restrict__ A,
                                 const float* __restrict__ W,
                                 const float* __restrict__ bias,
                                 float* __restrict__ out,
                                 int use_gelu)
{
    __shared__ float As[32][36];   // pad 36 floats (144B, 16B-aligned rows)
    __shared__ float Bs[32][64];

    const int m0  = blockIdx.x * 32;
    const int tid = threadIdx.x;
    const int ty  = tid >> 4;       // 0..15
    const int tx  = tid & 15;       // 0..15

    float acc[2][4];
    #pragma unroll
    for (int i = 0; i < 2; i++)
        #pragma unroll
        for (int j = 0; j < 4; j++) acc[i][j] = 0.0f;

    for (int kt = 0; kt < C_ / 32; kt++) {
        const int k0 = kt * 32;
        // A tile: 32x32 = 256 float4, 1 per thread
        {
            int r  = tid >> 3;         // 0..31
            int c4 = tid & 7;          // 0..7
            float4 v = *(const float4*)(A + (size_t)(m0 + r) * C_ + k0 + 4 * c4);
            *(float4*)&As[r][4 * c4] = v;
        }
        // B tile: 32x64 = 512 float4, 2 per thread
        #pragma unroll
        for (int rep = 0; rep < 2; rep++) {
            int idx = tid + 256 * rep;
            int k   = idx >> 4;        // 0..31
            int c4  = idx & 15;        // 0..15
            float4 v = *(const float4*)(W + (size_t)(k0 + k) * R_ + 4 * c4);
            *(float4*)&Bs[k][4 * c4] = v;
        }
        __syncthreads();

        #pragma unroll
        for (int kk = 0; kk < 32; kk++) {
            float a0 = As[2 * ty + 0][kk];
            float a1 = As[2 * ty + 1][kk];
            float4 b = *(const float4*)&Bs[kk][4 * tx];
            acc[0][0] += a0 * b.x; acc[0][1] += a0 * b.y;
            acc[0][2] += a0 * b.z; acc[0][3] += a0 * b.w;
            acc[1][0] += a1 * b.x; acc[1][1] += a1 * b.y;
            acc[1][2] += a1 * b.z; acc[1][3] += a1 * b.w;
        }
        __syncthreads();
    }

    #pragma unroll
    for (int i = 0; i < 2; i++) {
        float4 v;
        float* p = &acc[i][0];
        #pragma unroll
        for (int j = 0; j < 4; j++) {
            float x = p[j];
            if (bias) x += bias[4 * tx + j];
            if (use_gelu) x = gelu_exact(x);
            p[j] = x;
        }
        v.x = p[0]; v.y = p[1]; v.z = p[2]; v.w = p[3];
        *(float4*)(out + (size_t)(m0 + 2 * ty + i) * R_ + 4 * tx) = v;
    }
}

// ---------------------------------------------------------------------------
// GEMM "expand": [M,64] @ [64,Nout] (+bias) -> [M,Nout]
// Block: 64x64 tile, 256 threads, 4x4 per thread, K=64 fully in smem
// ---------------------------------------------------------------------------
__global__ void gemm_expand_kernel(const float* __restrict__ A,
                                   const float* __restrict__ W,
                                   const float* __restrict__ bias,
                                   float* __restrict__ out,
                                   int Nout)
{
    __shared__ float As[64][68];   // pad 68 (272B rows, 16B-aligned)
    __shared__ float Bs[64][64];

    const int n0  = blockIdx.x * 64;
    const int m0  = blockIdx.y * 64;
    const int tid = threadIdx.x;
    const int ty  = tid >> 4;
    const int tx  = tid & 15;

    // A tile: 64x64 = 1024 float4, 4 per thread
    #pragma unroll
    for (int rep = 0; rep < 4; rep++) {
        int idx = tid + 256 * rep;
        int r   = idx >> 4;
        int c4  = idx & 15;
        *(float4*)&As[r][4 * c4] =
            *(const float4*)(A + (size_t)(m0 + r) * R_ + 4 * c4);
    }
    // B tile: 64x64, 4 per thread
    #pragma unroll
    for (int rep = 0; rep < 4; rep++) {
        int idx = tid + 256 * rep;
        int k   = idx >> 4;
        int c4  = idx & 15;
        *(float4*)&Bs[k][4 * c4] =
            *(const float4*)(W + (size_t)k * Nout + n0 + 4 * c4);
    }
    __syncthreads();

    float acc[4][4];
    #pragma unroll
    for (int i = 0; i < 4; i++)
        #pragma unroll
        for (int j = 0; j < 4; j++) acc[i][j] = 0.0f;

    #pragma unroll
    for (int kk = 0; kk < 64; kk++) {
        float a[4];
        #pragma unroll
        for (int i = 0; i < 4; i++) a[i] = As[4 * ty + i][kk];
        float4 b = *(const float4*)&Bs[kk][4 * tx];
        #pragma unroll
        for (int i = 0; i < 4; i++) {
            acc[i][0] += a[i] * b.x; acc[i][1] += a[i] * b.y;
            acc[i][2] += a[i] * b.z; acc[i][3] += a[i] * b.w;
        }
    }

    #pragma unroll
    for (int i = 0; i < 4; i++) {
        float4 v;
        float* p = &acc[i][0];
        if (bias) {
            #pragma unroll
            for (int j = 0; j < 4; j++) p[j] += bias[n0 + 4 * tx + j];
        }
        v.x = p[0]; v.y = p[1]; v.z = p[2]; v.w = p[3];
        *(float4*)(out + (size_t)(m0 + 4 * ty + i) * Nout + n0 + 4 * tx) = v;
    }
}

// ---------------------------------------------------------------------------
// Flash attention, fp32, online softmax.
// Grid: (32 q-tiles, 32 bh).  Block 256 threads (16x16), 64x64 tiles.
// Column mapping c = tx + 16*j  -> conflict-free LDS.128 on K/V tiles.
// ---------------------------------------------------------------------------
#define FLASH_SMEM (4 * 64 * 68 * 4)

__global__ void flash_kernel(const float* __restrict__ qkv,
                             float* __restrict__ attn_out)
{
    extern __shared__ float sm[];
    float* Qs = sm;                 // [64][68]
    float* Ks = Qs + 64 * 68;
    float* Vs = Ks + 64 * 68;
    float* Ps = Vs + 64 * 68;

    const int qt  = blockIdx.x;     // 0..31
    const int bh  = blockIdx.y;     // 0..31
    const int b   = bh >> 4;
    const int h   = bh & 15;
    const int tid = threadIdx.x;
    const int ty  = tid >> 4;
    const int tx  = tid & 15;
    const float scale = 0.125f;     // 64^-0.5

    const float* qbase = qkv + (size_t)(b * N_ + qt * 64) * QKV3_ + h * DH_;
    const float* kbase = qkv + (size_t)(b * N_) * QKV3_ + C_ + h * DH_;
    const float* vbase = kbase + C_;

    // Load (pre-scaled) Q tile
    #pragma unroll
    for (int rep = 0; rep < 4; rep++) {
        int idx = tid + 256 * rep;
        int r   = idx >> 4;
        int c4  = idx & 15;
        float4 v = *(const float4*)(qbase + (size_t)r * QKV3_ + 4 * c4);
        v.x *= scale; v.y *= scale; v.z *= scale; v.w *= scale;
        *(float4*)&Qs[r * 68 + 4 * c4] = v;
    }

    float mrow[4], lrow[4], o[4][4];
    #pragma unroll
    for (int i = 0; i < 4; i++) {
        mrow[i] = -1e30f; lrow[i] = 0.0f;
        #pragma unroll
        for (int j = 0; j < 4; j++) o[i][j] = 0.0f;
    }

    for (int t = 0; t < N_ / 64; t++) {
        __syncthreads();   // prev PV done reading Ps/Vs; Q smem visible (t=0)
        #pragma unroll
        for (int rep = 0; rep < 4; rep++) {
            int idx = tid + 256 * rep;
            int r   = idx >> 4;
            int c4  = idx & 15;
            size_t go = (size_t)(t * 64 + r) * QKV3_ + 4 * c4;
            *(float4*)&Ks[r * 68 + 4 * c4] = *(const float4*)(kbase + go);
            *(float4*)&Vs[r * 68 + 4 * c4] = *(const float4*)(vbase + go);
        }
        __syncthreads();

        // S = Q K^T  (rows 4ty+i, cols tx+16j)
        float s[4][4];
        #pragma unroll
        for (int i = 0; i < 4; i++)
            #pragma unroll
            for (int j = 0; j < 4; j++) s[i][j] = 0.0f;

        #pragma unroll
        for (int d4 = 0; d4 < 16; d4++) {
            float4 a[4], bb[4];
            #pragma unroll
            for (int i = 0; i < 4; i++)
                a[i] = *(const float4*)&Qs[(4 * ty + i) * 68 + 4 * d4];
            #pragma unroll
            for (int j = 0; j < 4; j++)
                bb[j] = *(const float4*)&Ks[(tx + 16 * j) * 68 + 4 * d4];
            #pragma unroll
            for (int i = 0; i < 4; i++)
                #pragma unroll
                for (int j = 0; j < 4; j++)
                    s[i][j] += a[i].x * bb[j].x + a[i].y * bb[j].y +
                               a[i].z * bb[j].z + a[i].w * bb[j].w;
        }

        // Online softmax (row stats shared by the 16 tx lanes of each row)
        #pragma unroll
        for (int i = 0; i < 4; i++) {
            float tm = fmaxf(fmaxf(s[i][0], s[i][1]), fmaxf(s[i][2], s[i][3]));
            #pragma unroll
            for (int off = 8; off; off >>= 1)
                tm = fmaxf(tm, __shfl_xor_sync(0xffffffffu, tm, off));
            float mn   = fmaxf(mrow[i], tm);
            float corr = __expf(mrow[i] - mn);
            float rs = 0.0f;
            #pragma unroll
            for (int j = 0; j < 4; j++) {
                s[i][j] = __expf(s[i][j] - mn);
                rs += s[i][j];
            }
            #pragma unroll
            for (int off = 8; off; off >>= 1)
                rs += __shfl_xor_sync(0xffffffffu, rs, off);
            lrow[i] = lrow[i] * corr + rs;
            mrow[i] = mn;
            #pragma unroll
            for (int j = 0; j < 4; j++) o[i][j] *= corr;
        }

        // Store P (conflict-free: lanes tx consecutive)
        #pragma unroll
        for (int i = 0; i < 4; i++)
            #pragma unroll
            for (int j = 0; j < 4; j++)
                Ps[(4 * ty + i) * 68 + tx + 16 * j] = s[i][j];
        __syncthreads();

        // O += P V
        #pragma unroll
        for (int k4 = 0; k4 < 16; k4++) {
            float pr[4][4];
            #pragma unroll
            for (int i = 0; i < 4; i++) {
                float4 p4 = *(const float4*)&Ps[(4 * ty + i) * 68 + 4 * k4];
                pr[i][0] = p4.x; pr[i][1] = p4.y; pr[i][2] = p4.z; pr[i][3] = p4.w;
            }
            #pragma unroll
            for (int kk = 0; kk < 4; kk++) {
                float vv[4];
                #pragma unroll
                for (int j = 0; j < 4; j++)
                    vv[j] = Vs[(4 * k4 + kk) * 68 + tx + 16 * j];
                #pragma unroll
                for (int i = 0; i < 4; i++)
                    #pragma unroll
                    for (int j = 0; j < 4; j++)
                        o[i][j] += pr[i][kk] * vv[j];
            }
        }
    }

    // Epilogue: divide by l, write [B,N,H*Dh]
    #pragma unroll
    for (int i = 0; i < 4; i++) {
        float inv = 1.0f / lrow[i];
        int row = b * N_ + qt * 64 + 4 * ty + i;
        #pragma unroll
        for (int j = 0; j < 4; j++)
            attn_out[(size_t)row * C_ + h * DH_ + tx + 16 * j] = o[i][j] * inv;
    }
}

// ---------------------------------------------------------------------------
extern "C" void kernel_launch(void* const* d_in, const int* in_sizes, int n_in,
                              void* d_out, int out_size)
{
    const float* x        = (const float*)d_in[0];
    const float* w_qkv_a  = (const float*)d_in[1];
    const float* w_qkv_b  = (const float*)d_in[2];
    const float* w_proj_a = (const float*)d_in[3];
    const float* b_proj_a = (const float*)d_in[4];
    const float* w_proj_b = (const float*)d_in[5];
    const float* b_proj_b = (const float*)d_in[6];
    float* out = (float*)d_out;

    float *h1, *qkv, *attn, *h2;
    cudaGetSymbolAddress((void**)&h1,   g_h1);
    cudaGetSymbolAddress((void**)&qkv,  g_qkv);
    cudaGetSymbolAddress((void**)&attn, g_attn);
    cudaGetSymbolAddress((void**)&h2,   g_h2);

    cudaFuncSetAttribute(flash_kernel,
                         cudaFuncAttributeMaxDynamicSharedMemorySize, FLASH_SMEM);

    // 1) h1 = gelu(x @ w_qkv_a)
    gemm_rank_kernel<<<M_ / 32, 256>>>(x, w_qkv_a, nullptr, h1, 1);
    // 2) qkv = h1 @ w_qkv_b
    gemm_expand_kernel<<<dim3(QKV3_ / 64, M_ / 64), 256>>>(h1, w_qkv_b, nullptr, qkv, QKV3_);
    // 3) attention
    flash_kernel<<<dim3(N_ / 64, B_ * H_), 256, FLASH_SMEM>>>(qkv, attn);
    // 4) h2 = gelu(attn @ w_proj_a + b_proj_a)
    gemm_rank_kernel<<<M_ / 32, 256>>>(attn, w_proj_a, b_proj_a, h2, 1);
    // 5) out = h2 @ w_proj_b + b_proj_b
    gemm_expand_kernel<<<dim3(C_ / 64, M_ / 64), 256>>>(h2, w_proj_b, b_proj_b, out, C_);
}

// round 4
// speedup vs baseline: 2.8035x; 2.8035x over previous
#include <cuda_runtime.h>
#include <cuda_bf16.h>
#include <math.h>
#include <stdint.h>

// Problem constants
#define B_  2
#define N_  2048
#define C_  1024
#define R_  64
#define H_  16
#define DH_ 64
#define M_  (B_ * N_)          // 4096 rows
#define QKV3_ (3 * C_)         // 3072

// Scratch (device globals: allocation-free)
__device__ float g_h1[M_ * R_];                    // 1 MB
__device__ __nv_bfloat16 g_qkv_bf[M_ * QKV3_];     // 24 MB
__device__ float g_attn[M_ * C_];                  // 16 MB
__device__ float g_h2[M_ * R_];                    // 1 MB

__device__ __forceinline__ float gelu_exact(float x) {
    return 0.5f * x * (1.0f + erff(x * 0.70710678118654752f));
}

__device__ __forceinline__ uint32_t pack_bf16(float lo, float hi) {
    uint32_t r;
    asm("cvt.rn.bf16x2.f32 %0, %1, %2;" : "=r"(r) : "f"(hi), "f"(lo));
    return r;
}

__device__ __forceinline__ void mma16816(float* c, const uint32_t* a,
                                         uint32_t b0, uint32_t b1) {
    asm volatile(
        "mma.sync.aligned.m16n8k16.row.col.f32.bf16.bf16.f32 "
        "{%0,%1,%2,%3}, {%4,%5,%6,%7}, {%8,%9}, {%0,%1,%2,%3};"
        : "+f"(c[0]), "+f"(c[1]), "+f"(c[2]), "+f"(c[3])
        : "r"(a[0]), "r"(a[1]), "r"(a[2]), "r"(a[3]), "r"(b0), "r"(b1));
}

// ---------------------------------------------------------------------------
// GEMM "rank": [M,1024] @ [1024,64] (+bias) (gelu) -> [M,64]  (fp32)
// ---------------------------------------------------------------------------
__global__ void gemm_rank_kernel(const float* __restrict__ A,
                                 const float* __restrict__ W,
                                 const float* __restrict__ bias,
                                 float* __restrict__ out,
                                 int use_gelu)
{
    __shared__ float As[32][36];
    __shared__ float Bs[32][64];

    const int m0  = blockIdx.x * 32;
    const int tid = threadIdx.x;
    const int ty  = tid >> 4;
    const int tx  = tid & 15;

    float acc[2][4];
    #pragma unroll
    for (int i = 0; i < 2; i++)
        #pragma unroll
        for (int j = 0; j < 4; j++) acc[i][j] = 0.0f;

    for (int kt = 0; kt < C_ / 32; kt++) {
        const int k0 = kt * 32;
        {
            int r  = tid >> 3;
            int c4 = tid & 7;
            float4 v = *(const float4*)(A + (size_t)(m0 + r) * C_ + k0 + 4 * c4);
            *(float4*)&As[r][4 * c4] = v;
        }
        #pragma unroll
        for (int rep = 0; rep < 2; rep++) {
            int idx = tid + 256 * rep;
            int k   = idx >> 4;
            int c4  = idx & 15;
            float4 v = *(const float4*)(W + (size_t)(k0 + k) * R_ + 4 * c4);
            *(float4*)&Bs[k][4 * c4] = v;
        }
        __syncthreads();

        #pragma unroll
        for (int kk = 0; kk < 32; kk++) {
            float a0 = As[2 * ty + 0][kk];
            float a1 = As[2 * ty + 1][kk];
            float4 b = *(const float4*)&Bs[kk][4 * tx];
            acc[0][0] += a0 * b.x; acc[0][1] += a0 * b.y;
            acc[0][2] += a0 * b.z; acc[0][3] += a0 * b.w;
            acc[1][0] += a1 * b.x; acc[1][1] += a1 * b.y;
            acc[1][2] += a1 * b.z; acc[1][3] += a1 * b.w;
        }
        __syncthreads();
    }

    #pragma unroll
    for (int i = 0; i < 2; i++) {
        float4 v;
        float* p = &acc[i][0];
        #pragma unroll
        for (int j = 0; j < 4; j++) {
            float x = p[j];
            if (bias) x += bias[4 * tx + j];
            if (use_gelu) x = gelu_exact(x);
            p[j] = x;
        }
        v.x = p[0]; v.y = p[1]; v.z = p[2]; v.w = p[3];
        *(float4*)(out + (size_t)(m0 + 2 * ty + i) * R_ + 4 * tx) = v;
    }
}

// ---------------------------------------------------------------------------
// GEMM "expand" fp32 out: [M,64] @ [64,Nout] (+bias) -> [M,Nout]
// ---------------------------------------------------------------------------
__global__ void gemm_expand_kernel(const float* __restrict__ A,
                                   const float* __restrict__ W,
                                   const float* __restrict__ bias,
                                   float* __restrict__ out,
                                   int Nout)
{
    __shared__ float As[64][68];
    __shared__ float Bs[64][64];

    const int n0  = blockIdx.x * 64;
    const int m0  = blockIdx.y * 64;
    const int tid = threadIdx.x;
    const int ty  = tid >> 4;
    const int tx  = tid & 15;

    #pragma unroll
    for (int rep = 0; rep < 4; rep++) {
        int idx = tid + 256 * rep;
        int r   = idx >> 4;
        int c4  = idx & 15;
        *(float4*)&As[r][4 * c4] =
            *(const float4*)(A + (size_t)(m0 + r) * R_ + 4 * c4);
    }
    #pragma unroll
    for (int rep = 0; rep < 4; rep++) {
        int idx = tid + 256 * rep;
        int k   = idx >> 4;
        int c4  = idx & 15;
        *(float4*)&Bs[k][4 * c4] =
            *(const float4*)(W + (size_t)k * Nout + n0 + 4 * c4);
    }
    __syncthreads();

    float acc[4][4];
    #pragma unroll
    for (int i = 0; i < 4; i++)
        #pragma unroll
        for (int j = 0; j < 4; j++) acc[i][j] = 0.0f;

    #pragma unroll
    for (int kk = 0; kk < 64; kk++) {
        float a[4];
        #pragma unroll
        for (int i = 0; i < 4; i++) a[i] = As[4 * ty + i][kk];
        float4 b = *(const float4*)&Bs[kk][4 * tx];
        #pragma unroll
        for (int i = 0; i < 4; i++) {
            acc[i][0] += a[i] * b.x; acc[i][1] += a[i] * b.y;
            acc[i][2] += a[i] * b.z; acc[i][3] += a[i] * b.w;
        }
    }

    #pragma unroll
    for (int i = 0; i < 4; i++) {
        float4 v;
        float* p = &acc[i][0];
        if (bias) {
            #pragma unroll
            for (int j = 0; j < 4; j++) p[j] += bias[n0 + 4 * tx + j];
        }
        v.x = p[0]; v.y = p[1]; v.z = p[2]; v.w = p[3];
        *(float4*)(out + (size_t)(m0 + 4 * ty + i) * Nout + n0 + 4 * tx) = v;
    }
}

// ---------------------------------------------------------------------------
// GEMM "expand" bf16 out (for qkv): [M,64] @ [64,3072] -> bf16 [M,3072]
// ---------------------------------------------------------------------------
__global__ void gemm_expand_bf16_kernel(const float* __restrict__ A,
                                        const float* __restrict__ W,
                                        __nv_bfloat16* __restrict__ out,
                                        int Nout)
{
    __shared__ float As[64][68];
    __shared__ float Bs[64][64];

    const int n0  = blockIdx.x * 64;
    const int m0  = blockIdx.y * 64;
    const int tid = threadIdx.x;
    const int ty  = tid >> 4;
    const int tx  = tid & 15;

    #pragma unroll
    for (int rep = 0; rep < 4; rep++) {
        int idx = tid + 256 * rep;
        int r   = idx >> 4;
        int c4  = idx & 15;
        *(float4*)&As[r][4 * c4] =
            *(const float4*)(A + (size_t)(m0 + r) * R_ + 4 * c4);
    }
    #pragma unroll
    for (int rep = 0; rep < 4; rep++) {
        int idx = tid + 256 * rep;
        int k   = idx >> 4;
        int c4  = idx & 15;
        *(float4*)&Bs[k][4 * c4] =
            *(const float4*)(W + (size_t)k * Nout + n0 + 4 * c4);
    }
    __syncthreads();

    float acc[4][4];
    #pragma unroll
    for (int i = 0; i < 4; i++)
        #pragma unroll
        for (int j = 0; j < 4; j++) acc[i][j] = 0.0f;

    #pragma unroll
    for (int kk = 0; kk < 64; kk++) {
        float a[4];
        #pragma unroll
        for (int i = 0; i < 4; i++) a[i] = As[4 * ty + i][kk];
        float4 b = *(const float4*)&Bs[kk][4 * tx];
        #pragma unroll
        for (int i = 0; i < 4; i++) {
            acc[i][0] += a[i] * b.x; acc[i][1] += a[i] * b.y;
            acc[i][2] += a[i] * b.z; acc[i][3] += a[i] * b.w;
        }
    }

    #pragma unroll
    for (int i = 0; i < 4; i++) {
        uint2 u;
        u.x = pack_bf16(acc[i][0], acc[i][1]);
        u.y = pack_bf16(acc[i][2], acc[i][3]);
        *(uint2*)(out + (size_t)(m0 + 4 * ty + i) * Nout + n0 + 4 * tx) = u;
    }
}

// ---------------------------------------------------------------------------
// Flash attention, bf16 mma.sync (m16n8k16), fp32 accum, online softmax.
// Grid: (32 q-tiles, 32 bh). Block 128 threads = 4 warps; warp w owns q rows
// [16w, 16w+16). Br=Bc=64, Dh=64. P stays in registers (C->A frag remap).
// K smem row-padded to 72 bf16 (conflict-free LDS.32 frags).
// V stored transposed as kv-pairs: uint32 Vt[dh][kvp ^ (dh>>3)] (swizzled).
// ---------------------------------------------------------------------------
__global__ void __launch_bounds__(128)
flash_mma_kernel(const __nv_bfloat16* __restrict__ qkv,
                 float* __restrict__ attn_out)
{
    __shared__ __nv_bfloat16 Qs[64][72];
    __shared__ __nv_bfloat16 Ks[64][72];
    __shared__ uint32_t      Vt[64][36];

    const int qt   = blockIdx.x;
    const int bh   = blockIdx.y;
    const int b    = bh >> 4;
    const int h    = bh & 15;
    const int tid  = threadIdx.x;
    const int w    = tid >> 5;
    const int lane = tid & 31;
    const int g    = lane >> 2;      // 0..7
    const int tig  = lane & 3;       // 0..3

    const __nv_bfloat16* qbase = qkv + (size_t)(b * N_ + qt * 64) * QKV3_ + h * DH_;
    const __nv_bfloat16* kbase = qkv + (size_t)(b * N_) * QKV3_ + C_ + h * DH_;
    const __nv_bfloat16* vbase = kbase + C_;

    // Load Q tile (64x64 bf16)
    #pragma unroll
    for (int rep = 0; rep < 4; rep++) {
        int idx = tid + 128 * rep;
        int r = idx >> 3, c8 = idx & 7;
        *(uint4*)&Qs[r][8 * c8] = *(const uint4*)(qbase + (size_t)r * QKV3_ + 8 * c8);
    }
    __syncthreads();

    // Q fragments: 4 k-steps x 4 regs, register-resident for the whole kernel
    uint32_t qf[4][4];
    #pragma unroll
    for (int ks = 0; ks < 4; ks++) {
        qf[ks][0] = *(const uint32_t*)&Qs[16 * w + g    ][16 * ks + 2 * tig    ];
        qf[ks][1] = *(const uint32_t*)&Qs[16 * w + g + 8][16 * ks + 2 * tig    ];
        qf[ks][2] = *(const uint32_t*)&Qs[16 * w + g    ][16 * ks + 2 * tig + 8];
        qf[ks][3] = *(const uint32_t*)&Qs[16 * w + g + 8][16 * ks + 2 * tig + 8];
    }

    float o[8][4];
    #pragma unroll
    for (int n = 0; n < 8; n++)
        #pragma unroll
        for (int j = 0; j < 4; j++) o[n][j] = 0.0f;
    float m0 = -1e30f, m1 = -1e30f, l0 = 0.0f, l1 = 0.0f;
    const float scale = 0.125f;   // Dh^-0.5

    for (int t = 0; t < N_ / 64; t++) {
        __syncthreads();   // previous iteration done reading Ks/Vt
        // K tile
        #pragma unroll
        for (int rep = 0; rep < 4; rep++) {
            int idx = tid + 128 * rep;
            int r = idx >> 3, c8 = idx & 7;
            *(uint4*)&Ks[r][8 * c8] =
                *(const uint4*)(kbase + (size_t)(t * 64 + r) * QKV3_ + 8 * c8);
        }
        // V tile, transposed into kv-pair uint32s with XOR swizzle
        #pragma unroll
        for (int rep = 0; rep < 2; rep++) {
            int idx = tid + 128 * rep;
            int rp = idx >> 3, c8 = idx & 7;   // rp: kv-pair 0..31
            uint4 v0 = *(const uint4*)(vbase + (size_t)(t * 64 + 2 * rp    ) * QKV3_ + 8 * c8);
            uint4 v1 = *(const uint4*)(vbase + (size_t)(t * 64 + 2 * rp + 1) * QKV3_ + 8 * c8);
            const unsigned short* p0 = (const unsigned short*)&v0;
            const unsigned short* p1 = (const unsigned short*)&v1;
            #pragma unroll
            for (int e = 0; e < 8; e++)
                Vt[8 * c8 + e][rp ^ c8] = (uint32_t)p0[e] | ((uint32_t)p1[e] << 16);
        }
        __syncthreads();

        // S = Q K^T  (per warp: 16 x 64, 8 n-tiles of 8)
        float s[8][4];
        #pragma unroll
        for (int n = 0; n < 8; n++)
            #pragma unroll
            for (int j = 0; j < 4; j++) s[n][j] = 0.0f;

        #pragma unroll
        for (int ks = 0; ks < 4; ks++)
            #pragma unroll
            for (int n = 0; n < 8; n++) {
                uint32_t b0 = *(const uint32_t*)&Ks[8 * n + g][16 * ks + 2 * tig    ];
                uint32_t b1 = *(const uint32_t*)&Ks[8 * n + g][16 * ks + 2 * tig + 8];
                mma16816(s[n], qf[ks], b0, b1);
            }

        // Online softmax. Thread holds rows r0 = 16w+g (s[.][0..1]) and
        // r1 = r0+8 (s[.][2..3]); lanes sharing a row are the quad (xor 1,2).
        float mx0 = -1e30f, mx1 = -1e30f;
        #pragma unroll
        for (int n = 0; n < 8; n++) {
            s[n][0] *= scale; s[n][1] *= scale; s[n][2] *= scale; s[n][3] *= scale;
            mx0 = fmaxf(mx0, fmaxf(s[n][0], s[n][1]));
            mx1 = fmaxf(mx1, fmaxf(s[n][2], s[n][3]));
        }
        mx0 = fmaxf(mx0, __shfl_xor_sync(0xffffffffu, mx0, 1));
        mx0 = fmaxf(mx0, __shfl_xor_sync(0xffffffffu, mx0, 2));
        mx1 = fmaxf(mx1, __shfl_xor_sync(0xffffffffu, mx1, 1));
        mx1 = fmaxf(mx1, __shfl_xor_sync(0xffffffffu, mx1, 2));

        float mn0 = fmaxf(m0, mx0), mn1 = fmaxf(m1, mx1);
        float cr0 = __expf(m0 - mn0), cr1 = __expf(m1 - mn1);
        m0 = mn0; m1 = mn1;

        float rs0 = 0.0f, rs1 = 0.0f;
        #pragma unroll
        for (int n = 0; n < 8; n++) {
            s[n][0] = __expf(s[n][0] - mn0);
            s[n][1] = __expf(s[n][1] - mn0);
            s[n][2] = __expf(s[n][2] - mn1);
            s[n][3] = __expf(s[n][3] - mn1);
            rs0 += s[n][0] + s[n][1];
            rs1 += s[n][2] + s[n][3];
        }
        rs0 += __shfl_xor_sync(0xffffffffu, rs0, 1);
        rs0 += __shfl_xor_sync(0xffffffffu, rs0, 2);
        rs1 += __shfl_xor_sync(0xffffffffu, rs1, 1);
        rs1 += __shfl_xor_sync(0xffffffffu, rs1, 2);
        l0 = l0 * cr0 + rs0;
        l1 = l1 * cr1 + rs1;
        #pragma unroll
        for (int n = 0; n < 8; n++) {
            o[n][0] *= cr0; o[n][1] *= cr0; o[n][2] *= cr1; o[n][3] *= cr1;
        }

        // O += P V  (P converted to bf16 A-fragments directly from S regs)
        #pragma unroll
        for (int ks = 0; ks < 4; ks++) {
            uint32_t a[4];
            a[0] = pack_bf16(s[2 * ks    ][0], s[2 * ks    ][1]);
            a[1] = pack_bf16(s[2 * ks    ][2], s[2 * ks    ][3]);
            a[2] = pack_bf16(s[2 * ks + 1][0], s[2 * ks + 1][1]);
            a[3] = pack_bf16(s[2 * ks + 1][2], s[2 * ks + 1][3]);
            #pragma unroll
            for (int n = 0; n < 8; n++) {
                uint32_t b0 = Vt[8 * n + g][(8 * ks + tig    ) ^ n];
                uint32_t b1 = Vt[8 * n + g][(8 * ks + tig + 4) ^ n];
                mma16816(o[n], a, b0, b1);
            }
        }
    }

    // Epilogue
    float inv0 = 1.0f / l0, inv1 = 1.0f / l1;
    int row0 = b * N_ + qt * 64 + 16 * w + g;
    float* out0 = attn_out + (size_t)row0 * C_ + h * DH_;
    float* out1 = out0 + (size_t)8 * C_;
    #pragma unroll
    for (int n = 0; n < 8; n++) {
        *(float2*)(out0 + 8 * n + 2 * tig) = make_float2(o[n][0] * inv0, o[n][1] * inv0);
        *(float2*)(out1 + 8 * n + 2 * tig) = make_float2(o[n][2] * inv1, o[n][3] * inv1);
    }
}

// ---------------------------------------------------------------------------
extern "C" void kernel_launch(void* const* d_in, const int* in_sizes, int n_in,
                              void* d_out, int out_size)
{
    const float* x        = (const float*)d_in[0];
    const float* w_qkv_a  = (const float*)d_in[1];
    const float* w_qkv_b  = (const float*)d_in[2];
    const float* w_proj_a = (const float*)d_in[3];
    const float* b_proj_a = (const float*)d_in[4];
    const float* w_proj_b = (const float*)d_in[5];
    const float* b_proj_b = (const float*)d_in[6];
    float* out = (float*)d_out;

    float *h1, *attn, *h2;
    __nv_bfloat16* qkv;
    cudaGetSymbolAddress((void**)&h1,   g_h1);
    cudaGetSymbolAddress((void**)&qkv,  g_qkv_bf);
    cudaGetSymbolAddress((void**)&attn, g_attn);
    cudaGetSymbolAddress((void**)&h2,   g_h2);

    // 1) h1 = gelu(x @ w_qkv_a)
    gemm_rank_kernel<<<M_ / 32, 256>>>(x, w_qkv_a, nullptr, h1, 1);
    // 2) qkv = h1 @ w_qkv_b  (bf16 out)
    gemm_expand_bf16_kernel<<<dim3(QKV3_ / 64, M_ / 64), 256>>>(h1, w_qkv_b, qkv, QKV3_);
    // 3) attention (tensor-core flash)
    flash_mma_kernel<<<dim3(N_ / 64, B_ * H_), 128>>>(qkv, attn);
    // 4) h2 = gelu(attn @ w_proj_a + b_proj_a)
    gemm_rank_kernel<<<M_ / 32, 256>>>(attn, w_proj_a, b_proj_a, h2, 1);
    // 5) out = h2 @ w_proj_b + b_proj_b
    gemm_expand_kernel<<<dim3(C_ / 64, M_ / 64), 256>>>(h2, w_proj_b, b_proj_b, out, C_);
}

// round 5
// speedup vs baseline: 4.4850x; 1.5998x over previous
#include <cuda_runtime.h>
#include <cuda_bf16.h>
#include <math.h>
#include <stdint.h>

// Problem constants
#define B_  2
#define N_  2048
#define C_  1024
#define R_  64
#define H_  16
#define DH_ 64
#define M_  (B_ * N_)          // 4096 rows
#define QKV3_ (3 * C_)         // 3072

// Scratch (device globals: allocation-free)
__device__ float g_h1[M_ * R_];                    // 1 MB
__device__ __nv_bfloat16 g_qkv_bf[M_ * QKV3_];     // 24 MB
__device__ float g_attn[M_ * C_];                  // 16 MB
__device__ float g_h2[M_ * R_];                    // 1 MB

__device__ __forceinline__ float gelu_exact(float x) {
    return 0.5f * x * (1.0f + erff(x * 0.70710678118654752f));
}

__device__ __forceinline__ uint32_t pack_bf16(float lo, float hi) {
    uint32_t r;
    asm("cvt.rn.bf16x2.f32 %0, %1, %2;" : "=r"(r) : "f"(hi), "f"(lo));
    return r;
}

__device__ __forceinline__ void mma16816(float* c, const uint32_t* a,
                                         uint32_t b0, uint32_t b1) {
    asm volatile(
        "mma.sync.aligned.m16n8k16.row.col.f32.bf16.bf16.f32 "
        "{%0,%1,%2,%3}, {%4,%5,%6,%7}, {%8,%9}, {%0,%1,%2,%3};"
        : "+f"(c[0]), "+f"(c[1]), "+f"(c[2]), "+f"(c[3])
        : "r"(a[0]), "r"(a[1]), "r"(a[2]), "r"(a[3]), "r"(b0), "r"(b1));
}

__device__ __forceinline__ void ldsm_x4(uint32_t& r0, uint32_t& r1,
                                        uint32_t& r2, uint32_t& r3,
                                        uint32_t addr) {
    asm volatile("ldmatrix.sync.aligned.m8n8.x4.shared.b16 {%0,%1,%2,%3}, [%4];"
        : "=r"(r0), "=r"(r1), "=r"(r2), "=r"(r3) : "r"(addr));
}

__device__ __forceinline__ void ldsm_x4_t(uint32_t& r0, uint32_t& r1,
                                          uint32_t& r2, uint32_t& r3,
                                          uint32_t addr) {
    asm volatile("ldmatrix.sync.aligned.m8n8.x4.trans.shared.b16 {%0,%1,%2,%3}, [%4];"
        : "=r"(r0), "=r"(r1), "=r"(r2), "=r"(r3) : "r"(addr));
}

__device__ __forceinline__ void cp16(void* smem_dst, const void* gmem_src) {
    uint32_t s = (uint32_t)__cvta_generic_to_shared(smem_dst);
    asm volatile("cp.async.cg.shared.global [%0], [%1], 16;" :: "r"(s), "l"(gmem_src));
}

// ---------------------------------------------------------------------------
// GEMM "rank": [M,1024] @ [1024,64] (+bias) (gelu) -> [M,64]  (fp32)
// 2-stage cp.async pipeline; block 32 rows x 64 cols, 256 threads.
// ---------------------------------------------------------------------------
__global__ void __launch_bounds__(256)
gemm_rank_kernel(const float* __restrict__ A,
                 const float* __restrict__ W,
                 const float* __restrict__ bias,
                 float* __restrict__ out,
                 int use_gelu)
{
    __shared__ __align__(16) float As[2][32][36];
    __shared__ __align__(16) float Bs[2][32][64];

    const int m0  = blockIdx.x * 32;
    const int tid = threadIdx.x;
    const int ty  = tid >> 4;
    const int tx  = tid & 15;

    // load-index precompute
    const int ar  = tid >> 3;          // 0..31
    const int ac4 = tid & 7;           // 0..7
    const int bk  = tid >> 4;          // 0..15
    const int bc4 = tid & 15;          // 0..15

    const int NT = C_ / 32;

    // prologue: stage 0
    cp16(&As[0][ar][4 * ac4], A + (size_t)(m0 + ar) * C_ + 4 * ac4);
    cp16(&Bs[0][bk][4 * bc4],      W + (size_t)bk        * R_ + 4 * bc4);
    cp16(&Bs[0][bk + 16][4 * bc4], W + (size_t)(bk + 16) * R_ + 4 * bc4);
    asm volatile("cp.async.commit_group;");

    float acc[2][4];
    #pragma unroll
    for (int i = 0; i < 2; i++)
        #pragma unroll
        for (int j = 0; j < 4; j++) acc[i][j] = 0.0f;

    for (int kt = 0; kt < NT; kt++) {
        if (kt + 1 < NT) {
            const int k0 = (kt + 1) * 32;
            const int s  = (kt + 1) & 1;
            cp16(&As[s][ar][4 * ac4], A + (size_t)(m0 + ar) * C_ + k0 + 4 * ac4);
            cp16(&Bs[s][bk][4 * bc4],      W + (size_t)(k0 + bk)      * R_ + 4 * bc4);
            cp16(&Bs[s][bk + 16][4 * bc4], W + (size_t)(k0 + bk + 16) * R_ + 4 * bc4);
            asm volatile("cp.async.commit_group;");
            asm volatile("cp.async.wait_group 1;");
        } else {
            asm volatile("cp.async.wait_group 0;");
        }
        __syncthreads();

        const int s = kt & 1;
        #pragma unroll
        for (int kk = 0; kk < 32; kk++) {
            float a0 = As[s][2 * ty + 0][kk];
            float a1 = As[s][2 * ty + 1][kk];
            float4 b = *(const float4*)&Bs[s][kk][4 * tx];
            acc[0][0] += a0 * b.x; acc[0][1] += a0 * b.y;
            acc[0][2] += a0 * b.z; acc[0][3] += a0 * b.w;
            acc[1][0] += a1 * b.x; acc[1][1] += a1 * b.y;
            acc[1][2] += a1 * b.z; acc[1][3] += a1 * b.w;
        }
        __syncthreads();
    }

    #pragma unroll
    for (int i = 0; i < 2; i++) {
        float4 v;
        float* p = &acc[i][0];
        #pragma unroll
        for (int j = 0; j < 4; j++) {
            float x = p[j];
            if (bias) x += bias[4 * tx + j];
            if (use_gelu) x = gelu_exact(x);
            p[j] = x;
        }
        v.x = p[0]; v.y = p[1]; v.z = p[2]; v.w = p[3];
        *(float4*)(out + (size_t)(m0 + 2 * ty + i) * R_ + 4 * tx) = v;
    }
}

// ---------------------------------------------------------------------------
// GEMM "expand" fp32 out: [M,64] @ [64,Nout] (+bias) -> [M,Nout]
// ---------------------------------------------------------------------------
__global__ void __launch_bounds__(256)
gemm_expand_kernel(const float* __restrict__ A,
                   const float* __restrict__ W,
                   const float* __restrict__ bias,
                   float* __restrict__ out,
                   int Nout)
{
    __shared__ __align__(16) float As[64][68];
    __shared__ __align__(16) float Bs[64][64];

    const int n0  = blockIdx.x * 64;
    const int m0  = blockIdx.y * 64;
    const int tid = threadIdx.x;
    const int ty  = tid >> 4;
    const int tx  = tid & 15;

    #pragma unroll
    for (int rep = 0; rep < 4; rep++) {
        int idx = tid + 256 * rep;
        int r   = idx >> 4;
        int c4  = idx & 15;
        *(float4*)&As[r][4 * c4] =
            *(const float4*)(A + (size_t)(m0 + r) * R_ + 4 * c4);
    }
    #pragma unroll
    for (int rep = 0; rep < 4; rep++) {
        int idx = tid + 256 * rep;
        int k   = idx >> 4;
        int c4  = idx & 15;
        *(float4*)&Bs[k][4 * c4] =
            *(const float4*)(W + (size_t)k * Nout + n0 + 4 * c4);
    }
    __syncthreads();

    float acc[4][4];
    #pragma unroll
    for (int i = 0; i < 4; i++)
        #pragma unroll
        for (int j = 0; j < 4; j++) acc[i][j] = 0.0f;

    #pragma unroll
    for (int kk = 0; kk < 64; kk++) {
        float a[4];
        #pragma unroll
        for (int i = 0; i < 4; i++) a[i] = As[4 * ty + i][kk];
        float4 b = *(const float4*)&Bs[kk][4 * tx];
        #pragma unroll
        for (int i = 0; i < 4; i++) {
            acc[i][0] += a[i] * b.x; acc[i][1] += a[i] * b.y;
            acc[i][2] += a[i] * b.z; acc[i][3] += a[i] * b.w;
        }
    }

    #pragma unroll
    for (int i = 0; i < 4; i++) {
        float4 v;
        float* p = &acc[i][0];
        if (bias) {
            #pragma unroll
            for (int j = 0; j < 4; j++) p[j] += bias[n0 + 4 * tx + j];
        }
        v.x = p[0]; v.y = p[1]; v.z = p[2]; v.w = p[3];
        *(float4*)(out + (size_t)(m0 + 4 * ty + i) * Nout + n0 + 4 * tx) = v;
    }
}

// ---------------------------------------------------------------------------
// GEMM "expand" bf16 out (for qkv): [M,64] @ [64,3072] -> bf16 [M,3072]
// ---------------------------------------------------------------------------
__global__ void __launch_bounds__(256)
gemm_expand_bf16_kernel(const float* __restrict__ A,
                        const float* __restrict__ W,
                        __nv_bfloat16* __restrict__ out,
                        int Nout)
{
    __shared__ __align__(16) float As[64][68];
    __shared__ __align__(16) float Bs[64][64];

    const int n0  = blockIdx.x * 64;
    const int m0  = blockIdx.y * 64;
    const int tid = threadIdx.x;
    const int ty  = tid >> 4;
    const int tx  = tid & 15;

    #pragma unroll
    for (int rep = 0; rep < 4; rep++) {
        int idx = tid + 256 * rep;
        int r   = idx >> 4;
        int c4  = idx & 15;
        *(float4*)&As[r][4 * c4] =
            *(const float4*)(A + (size_t)(m0 + r) * R_ + 4 * c4);
    }
    #pragma unroll
    for (int rep = 0; rep < 4; rep++) {
        int idx = tid + 256 * rep;
        int k   = idx >> 4;
        int c4  = idx & 15;
        *(float4*)&Bs[k][4 * c4] =
            *(const float4*)(W + (size_t)k * Nout + n0 + 4 * c4);
    }
    __syncthreads();

    float acc[4][4];
    #pragma unroll
    for (int i = 0; i < 4; i++)
        #pragma unroll
        for (int j = 0; j < 4; j++) acc[i][j] = 0.0f;

    #pragma unroll
    for (int kk = 0; kk < 64; kk++) {
        float a[4];
        #pragma unroll
        for (int i = 0; i < 4; i++) a[i] = As[4 * ty + i][kk];
        float4 b = *(const float4*)&Bs[kk][4 * tx];
        #pragma unroll
        for (int i = 0; i < 4; i++) {
            acc[i][0] += a[i] * b.x; acc[i][1] += a[i] * b.y;
            acc[i][2] += a[i] * b.z; acc[i][3] += a[i] * b.w;
        }
    }

    #pragma unroll
    for (int i = 0; i < 4; i++) {
        uint2 u;
        u.x = pack_bf16(acc[i][0], acc[i][1]);
        u.y = pack_bf16(acc[i][2], acc[i][3]);
        *(uint2*)(out + (size_t)(m0 + 4 * ty + i) * Nout + n0 + 4 * tx) = u;
    }
}

// ---------------------------------------------------------------------------
// Flash attention, bf16 mma.sync (m16n8k16), fp32 accum, online softmax.
// Grid: (32 q-tiles, 32 bh). Block 128 threads = 4 warps; warp w owns q rows
// [16w, 16w+16). Br=Bc=64, Dh=64. P stays in registers (C->A frag remap).
// K/Q/V all in row-major smem padded to 72 bf16 (144B rows); all fragments
// fetched with ldmatrix.x4 (V via .trans -> no manual transpose).
// ---------------------------------------------------------------------------
#define ROWB 144   // 72 bf16 row pitch in bytes

__global__ void __launch_bounds__(128)
flash_mma_kernel(const __nv_bfloat16* __restrict__ qkv,
                 float* __restrict__ attn_out)
{
    __shared__ __align__(16) __nv_bfloat16 Qs[64][72];
    __shared__ __align__(16) __nv_bfloat16 Ks[64][72];
    __shared__ __align__(16) __nv_bfloat16 Vs[64][72];

    const int qt   = blockIdx.x;
    const int bh   = blockIdx.y;
    const int b    = bh >> 4;
    const int h    = bh & 15;
    const int tid  = threadIdx.x;
    const int w    = tid >> 5;
    const int lane = tid & 31;
    const int g    = lane >> 2;      // 0..7
    const int tig  = lane & 3;       // 0..3
    const int l8   = lane & 7;
    const int seg  = lane >> 3;      // 0..3

    // ldmatrix lane byte-offsets within a 4-tile group:
    // A/V-pattern:  tiles (r,c),(r+8,c),(r,c+8),(r+8,c+8)
    const uint32_t offA = (uint32_t)(((seg & 1) * 8 + l8) * ROWB + ((seg >> 1) & 1) * 16);
    // B(K)-pattern: tiles (r,c),(r,c+8),(r+8,c),(r+8,c+8)
    const uint32_t offB = (uint32_t)((((seg >> 1) & 1) * 8 + l8) * ROWB + (seg & 1) * 16);

    const uint32_t qsa = (uint32_t)__cvta_generic_to_shared(&Qs[0][0]) + offA;
    const uint32_t ksa = (uint32_t)__cvta_generic_to_shared(&Ks[0][0]) + offB;
    const uint32_t vsa = (uint32_t)__cvta_generic_to_shared(&Vs[0][0]) + offA;

    const __nv_bfloat16* qbase = qkv + (size_t)(b * N_ + qt * 64) * QKV3_ + h * DH_;
    const __nv_bfloat16* kbase = qkv + (size_t)(b * N_) * QKV3_ + C_ + h * DH_;
    const __nv_bfloat16* vbase = kbase + C_;

    // Load Q tile (64x64 bf16)
    #pragma unroll
    for (int rep = 0; rep < 4; rep++) {
        int idx = tid + 128 * rep;
        int r = idx >> 3, c8 = idx & 7;
        *(uint4*)&Qs[r][8 * c8] = *(const uint4*)(qbase + (size_t)r * QKV3_ + 8 * c8);
    }
    __syncthreads();

    // Q fragments, register-resident: qf[ks] = {a0,a1,a2,a3}
    uint32_t qf[4][4];
    #pragma unroll
    for (int ks = 0; ks < 4; ks++)
        ldsm_x4(qf[ks][0], qf[ks][1], qf[ks][2], qf[ks][3],
                qsa + (uint32_t)(w * 16 * ROWB + ks * 32));
    __syncthreads();   // done reading Qs region (it stays, but keep ordering)

    float o[8][4];
    #pragma unroll
    for (int n = 0; n < 8; n++)
        #pragma unroll
        for (int j = 0; j < 4; j++) o[n][j] = 0.0f;
    float m0 = -1e30f, m1 = -1e30f, l0 = 0.0f, l1 = 0.0f;
    const float scale = 0.125f;   // Dh^-0.5

    for (int t = 0; t < N_ / 64; t++) {
        __syncthreads();   // previous iteration done reading Ks/Vs
        #pragma unroll
        for (int rep = 0; rep < 4; rep++) {
            int idx = tid + 128 * rep;
            int r = idx >> 3, c8 = idx & 7;
            size_t go = (size_t)(t * 64 + r) * QKV3_ + 8 * c8;
            *(uint4*)&Ks[r][8 * c8] = *(const uint4*)(kbase + go);
            *(uint4*)&Vs[r][8 * c8] = *(const uint4*)(vbase + go);
        }
        __syncthreads();

        // S = Q K^T  (per warp: 16 x 64)
        float s[8][4];
        #pragma unroll
        for (int n = 0; n < 8; n++)
            #pragma unroll
            for (int j = 0; j < 4; j++) s[n][j] = 0.0f;

        #pragma unroll
        for (int ks = 0; ks < 4; ks++) {
            #pragma unroll
            for (int ntp = 0; ntp < 4; ntp++) {
                uint32_t b00, b01, b10, b11;
                ldsm_x4(b00, b01, b10, b11,
                        ksa + (uint32_t)(ntp * 16 * ROWB + ks * 32));
                mma16816(s[2 * ntp],     qf[ks], b00, b01);
                mma16816(s[2 * ntp + 1], qf[ks], b10, b11);
            }
        }

        // Online softmax (rows r0 = 16w+g, r1 = r0+8; quad = lanes xor 1,2)
        float mx0 = -1e30f, mx1 = -1e30f;
        #pragma unroll
        for (int n = 0; n < 8; n++) {
            s[n][0] *= scale; s[n][1] *= scale; s[n][2] *= scale; s[n][3] *= scale;
            mx0 = fmaxf(mx0, fmaxf(s[n][0], s[n][1]));
            mx1 = fmaxf(mx1, fmaxf(s[n][2], s[n][3]));
        }
        mx0 = fmaxf(mx0, __shfl_xor_sync(0xffffffffu, mx0, 1));
        mx0 = fmaxf(mx0, __shfl_xor_sync(0xffffffffu, mx0, 2));
        mx1 = fmaxf(mx1, __shfl_xor_sync(0xffffffffu, mx1, 1));
        mx1 = fmaxf(mx1, __shfl_xor_sync(0xffffffffu, mx1, 2));

        float mn0 = fmaxf(m0, mx0), mn1 = fmaxf(m1, mx1);
        float cr0 = __expf(m0 - mn0), cr1 = __expf(m1 - mn1);
        m0 = mn0; m1 = mn1;

        float rs0 = 0.0f, rs1 = 0.0f;
        #pragma unroll
        for (int n = 0; n < 8; n++) {
            s[n][0] = __expf(s[n][0] - mn0);
            s[n][1] = __expf(s[n][1] - mn0);
            s[n][2] = __expf(s[n][2] - mn1);
            s[n][3] = __expf(s[n][3] - mn1);
            rs0 += s[n][0] + s[n][1];
            rs1 += s[n][2] + s[n][3];
        }
        rs0 += __shfl_xor_sync(0xffffffffu, rs0, 1);
        rs0 += __shfl_xor_sync(0xffffffffu, rs0, 2);
        rs1 += __shfl_xor_sync(0xffffffffu, rs1, 1);
        rs1 += __shfl_xor_sync(0xffffffffu, rs1, 2);
        l0 = l0 * cr0 + rs0;
        l1 = l1 * cr1 + rs1;
        #pragma unroll
        for (int n = 0; n < 8; n++) {
            o[n][0] *= cr0; o[n][1] *= cr0; o[n][2] *= cr1; o[n][3] *= cr1;
        }

        // O += P V  (P->bf16 A-frags from regs; V B-frags via ldmatrix.trans)
        #pragma unroll
        for (int ks = 0; ks < 4; ks++) {
            uint32_t a[4];
            a[0] = pack_bf16(s[2 * ks    ][0], s[2 * ks    ][1]);
            a[1] = pack_bf16(s[2 * ks    ][2], s[2 * ks    ][3]);
            a[2] = pack_bf16(s[2 * ks + 1][0], s[2 * ks + 1][1]);
            a[3] = pack_bf16(s[2 * ks + 1][2], s[2 * ks + 1][3]);
            #pragma unroll
            for (int ntp = 0; ntp < 4; ntp++) {
                uint32_t b00, b01, b10, b11;
                ldsm_x4_t(b00, b01, b10, b11,
                          vsa + (uint32_t)(ks * 16 * ROWB + ntp * 32));
                mma16816(o[2 * ntp],     a, b00, b01);
                mma16816(o[2 * ntp + 1], a, b10, b11);
            }
        }
    }

    // Epilogue
    float inv0 = 1.0f / l0, inv1 = 1.0f / l1;
    int row0 = b * N_ + qt * 64 + 16 * w + g;
    float* out0 = attn_out + (size_t)row0 * C_ + h * DH_;
    float* out1 = out0 + (size_t)8 * C_;
    #pragma unroll
    for (int n = 0; n < 8; n++) {
        *(float2*)(out0 + 8 * n + 2 * tig) = make_float2(o[n][0] * inv0, o[n][1] * inv0);
        *(float2*)(out1 + 8 * n + 2 * tig) = make_float2(o[n][2] * inv1, o[n][3] * inv1);
    }
}

// ---------------------------------------------------------------------------
extern "C" void kernel_launch(void* const* d_in, const int* in_sizes, int n_in,
                              void* d_out, int out_size)
{
    const float* x        = (const float*)d_in[0];
    const float* w_qkv_a  = (const float*)d_in[1];
    const float* w_qkv_b  = (const float*)d_in[2];
    const float* w_proj_a = (const float*)d_in[3];
    const float* b_proj_a = (const float*)d_in[4];
    const float* w_proj_b = (const float*)d_in[5];
    const float* b_proj_b = (const float*)d_in[6];
    float* out = (float*)d_out;

    float *h1, *attn, *h2;
    __nv_bfloat16* qkv;
    cudaGetSymbolAddress((void**)&h1,   g_h1);
    cudaGetSymbolAddress((void**)&qkv,  g_qkv_bf);
    cudaGetSymbolAddress((void**)&attn, g_attn);
    cudaGetSymbolAddress((void**)&h2,   g_h2);

    // 1) h1 = gelu(x @ w_qkv_a)
    gemm_rank_kernel<<<M_ / 32, 256>>>(x, w_qkv_a, nullptr, h1, 1);
    // 2) qkv = h1 @ w_qkv_b  (bf16 out)
    gemm_expand_bf16_kernel<<<dim3(QKV3_ / 64, M_ / 64), 256>>>(h1, w_qkv_b, qkv, QKV3_);
    // 3) attention (tensor-core flash, ldmatrix fragment path)
    flash_mma_kernel<<<dim3(N_ / 64, B_ * H_), 128>>>(qkv, attn);
    // 4) h2 = gelu(attn @ w_proj_a + b_proj_a)
    gemm_rank_kernel<<<M_ / 32, 256>>>(attn, w_proj_a, b_proj_a, h2, 1);
    // 5) out = h2 @ w_proj_b + b_proj_b
    gemm_expand_kernel<<<dim3(C_ / 64, M_ / 64), 256>>>(h2, w_proj_b, b_proj_b, out, C_);
}

// round 8
// speedup vs baseline: 6.2383x; 1.3909x over previous
#include <cuda_runtime.h>
#include <cuda_bf16.h>
#include <math.h>
#include <stdint.h>

// Problem constants
#define B_  2
#define N_  2048
#define C_  1024
#define R_  64
#define H_  16
#define DH_ 64
#define M_  (B_ * N_)          // 4096 rows
#define QKV3_ (3 * C_)         // 3072

typedef __nv_bfloat16 bf16;

// Scratch (device globals: allocation-free)
__device__ bf16 g_x_bf [M_ * C_];        // 8 MB
__device__ bf16 g_wqa  [C_ * R_];
__device__ bf16 g_wqb  [R_ * QKV3_];
__device__ bf16 g_wpa  [C_ * R_];
__device__ bf16 g_wpb  [R_ * C_];
__device__ bf16 g_h1   [M_ * R_];
__device__ bf16 g_qkv  [M_ * QKV3_];     // 24 MB
__device__ bf16 g_attn [M_ * C_];        // 8 MB
__device__ bf16 g_h2   [M_ * R_];

__device__ __forceinline__ float gelu_exact(float x) {
    return 0.5f * x * (1.0f + erff(x * 0.70710678118654752f));
}

__device__ __forceinline__ uint32_t pack_bf16(float lo, float hi) {
    uint32_t r;
    asm("cvt.rn.bf16x2.f32 %0, %1, %2;" : "=r"(r) : "f"(hi), "f"(lo));
    return r;
}

__device__ __forceinline__ void mma16816(float* c, const uint32_t* a,
                                         uint32_t b0, uint32_t b1) {
    asm volatile(
        "mma.sync.aligned.m16n8k16.row.col.f32.bf16.bf16.f32 "
        "{%0,%1,%2,%3}, {%4,%5,%6,%7}, {%8,%9}, {%0,%1,%2,%3};"
        : "+f"(c[0]), "+f"(c[1]), "+f"(c[2]), "+f"(c[3])
        : "r"(a[0]), "r"(a[1]), "r"(a[2]), "r"(a[3]), "r"(b0), "r"(b1));
}

__device__ __forceinline__ void ldsm_x4(uint32_t& r0, uint32_t& r1,
                                        uint32_t& r2, uint32_t& r3,
                                        uint32_t addr) {
    asm volatile("ldmatrix.sync.aligned.m8n8.x4.shared.b16 {%0,%1,%2,%3}, [%4];"
        : "=r"(r0), "=r"(r1), "=r"(r2), "=r"(r3) : "r"(addr));
}

__device__ __forceinline__ void ldsm_x4_t(uint32_t& r0, uint32_t& r1,
                                          uint32_t& r2, uint32_t& r3,
                                          uint32_t addr) {
    asm volatile("ldmatrix.sync.aligned.m8n8.x4.trans.shared.b16 {%0,%1,%2,%3}, [%4];"
        : "=r"(r0), "=r"(r1), "=r"(r2), "=r"(r3) : "r"(addr));
}

__device__ __forceinline__ void cp16(void* smem_dst, const void* gmem_src) {
    uint32_t s = (uint32_t)__cvta_generic_to_shared(smem_dst);
    asm volatile("cp.async.cg.shared.global [%0], [%1], 16;" :: "r"(s), "l"(gmem_src));
}

// ---------------------------------------------------------------------------
// fp32 -> bf16 conversion (vectorized, n divisible by 4)
// ---------------------------------------------------------------------------
__global__ void cvt_kernel(const float* __restrict__ in, bf16* __restrict__ out,
                           int n4)
{
    int i = blockIdx.x * blockDim.x + threadIdx.x;
    if (i < n4) {
        float4 v = ((const float4*)in)[i];
        uint2 u;
        u.x = pack_bf16(v.x, v.y);
        u.y = pack_bf16(v.z, v.w);
        ((uint2*)out)[i] = u;
    }
}

// ---------------------------------------------------------------------------
// Tensor-core "rank" GEMM: out[M,64] = gelu(A[M,1024] @ W[1024,64] + bias)
// A,W bf16; accum fp32; out bf16. Block: 32 rows, 128 thr (4 warps),
// warp (w&1) picks 16-row half, (w>>1) picks 32-col half.
// 2-stage cp.async K pipeline, k-tile 64.
// ---------------------------------------------------------------------------
__global__ void __launch_bounds__(128)
gemm_rank_tc(const bf16* __restrict__ A, const bf16* __restrict__ W,
             const float* __restrict__ bias, bf16* __restrict__ out)
{
    __shared__ __align__(16) bf16 As[2][32][72];
    __shared__ __align__(16) bf16 Ws[2][64][72];

    const int m0   = blockIdx.x * 32;
    const int tid  = threadIdx.x;
    const int w    = tid >> 5;
    const int lane = tid & 31;
    const int g    = lane >> 2;
    const int tig  = lane & 3;
    const int l8   = lane & 7;
    const int seg  = lane >> 3;

    const uint32_t offA = (uint32_t)(((seg & 1) * 8 + l8) * 144 + ((seg >> 1) & 1) * 16);
    const uint32_t asa = (uint32_t)__cvta_generic_to_shared(&As[0][0][0]) + offA
                       + (uint32_t)((w & 1) * 16 * 144);
    const uint32_t wsa = (uint32_t)__cvta_generic_to_shared(&Ws[0][0][0]) + offA
                       + (uint32_t)((w >> 1) * 64);   // 32 cols * 2B

    // loader indices
    const int ar0 = tid >> 3, ac = (tid & 7) * 8;          // A: 2 cp16/thread
    const int ar1 = (tid + 128) >> 3;

    // prologue stage 0
    {
        cp16(&As[0][ar0][ac], A + (size_t)(m0 + ar0) * C_ + ac);
        cp16(&As[0][ar1][ac], A + (size_t)(m0 + ar1) * C_ + ac);
        #pragma unroll
        for (int rep = 0; rep < 4; rep++) {
            int idx = tid + 128 * rep;
            int r = idx >> 3, c = (idx & 7) * 8;
            cp16(&Ws[0][r][c], W + (size_t)r * R_ + c);
        }
        asm volatile("cp.async.commit_group;");
    }

    float c4[4][4];
    #pragma unroll
    for (int n = 0; n < 4; n++)
        #pragma unroll
        for (int j = 0; j < 4; j++) c4[n][j] = 0.0f;

    const int NT = C_ / 64;   // 16
    for (int kt = 0; kt < NT; kt++) {
        if (kt + 1 < NT) {
            const int s  = (kt + 1) & 1;
            const int k0 = (kt + 1) * 64;
            cp16(&As[s][ar0][ac], A + (size_t)(m0 + ar0) * C_ + k0 + ac);
            cp16(&As[s][ar1][ac], A + (size_t)(m0 + ar1) * C_ + k0 + ac);
            #pragma unroll
            for (int rep = 0; rep < 4; rep++) {
                int idx = tid + 128 * rep;
                int r = idx >> 3, c = (idx & 7) * 8;
                cp16(&Ws[s][r][c], W + (size_t)(k0 + r) * R_ + c);
            }
            asm volatile("cp.async.commit_group;");
            asm volatile("cp.async.wait_group 1;");
        } else {
            asm volatile("cp.async.wait_group 0;");
        }
        __syncthreads();

        const uint32_t ab = asa + (uint32_t)((kt & 1) * 32 * 144);
        const uint32_t wb = wsa + (uint32_t)((kt & 1) * 64 * 144);
        #pragma unroll
        for (int ks = 0; ks < 4; ks++) {
            uint32_t a[4];
            ldsm_x4(a[0], a[1], a[2], a[3], ab + (uint32_t)(ks * 32));
            #pragma unroll
            for (int ntp = 0; ntp < 2; ntp++) {
                uint32_t b00, b01, b10, b11;
                ldsm_x4_t(b00, b01, b10, b11,
                          wb + (uint32_t)(ks * 16 * 144 + ntp * 32));
                mma16816(c4[2 * ntp],     a, b00, b01);
                mma16816(c4[2 * ntp + 1], a, b10, b11);
            }
        }
        __syncthreads();
    }

    // epilogue: bias + gelu + bf16 store
    const int row0 = m0 + (w & 1) * 16 + g;
    const int cb   = (w >> 1) * 32;
    #pragma unroll
    for (int n = 0; n < 4; n++) {
        int col = cb + 8 * n + 2 * tig;
        float v0 = c4[n][0], v1 = c4[n][1], v2 = c4[n][2], v3 = c4[n][3];
        if (bias) {
            float b0 = bias[col], b1 = bias[col + 1];
            v0 += b0; v1 += b1; v2 += b0; v3 += b1;
        }
        v0 = gelu_exact(v0); v1 = gelu_exact(v1);
        v2 = gelu_exact(v2); v3 = gelu_exact(v3);
        *(uint32_t*)(out + (size_t)row0 * R_ + col)       = pack_bf16(v0, v1);
        *(uint32_t*)(out + (size_t)(row0 + 8) * R_ + col) = pack_bf16(v2, v3);
    }
}

// ---------------------------------------------------------------------------
// Tensor-core "expand" GEMM: out[M,Nout] = A[M,64] @ W[64,Nout] + bias
// A,W bf16; out bf16 (BF16OUT=1) or fp32. Block 64x128, 128 thr (4 warps).
// ---------------------------------------------------------------------------
template<int BF16OUT>
__global__ void __launch_bounds__(128)
gemm_expand_tc(const bf16* __restrict__ A, const bf16* __restrict__ W,
               const float* __restrict__ bias, void* __restrict__ outv,
               int Nout)
{
    __shared__ __align__(16) bf16 As[64][72];
    __shared__ __align__(16) bf16 Ws[64][136];

    const int n0   = blockIdx.x * 128;
    const int m0   = blockIdx.y * 64;
    const int tid  = threadIdx.x;
    const int w    = tid >> 5;
    const int lane = tid & 31;
    const int g    = lane >> 2;
    const int tig  = lane & 3;
    const int l8   = lane & 7;
    const int seg  = lane >> 3;

    // loads
    #pragma unroll
    for (int rep = 0; rep < 4; rep++) {
        int idx = tid + 128 * rep;
        int r = idx >> 3, c = (idx & 7) * 8;
        *(uint4*)&As[r][c] = *(const uint4*)(A + (size_t)(m0 + r) * R_ + c);
    }
    #pragma unroll
    for (int rep = 0; rep < 8; rep++) {
        int idx = tid + 128 * rep;
        int r = idx >> 4, c = (idx & 15) * 8;
        *(uint4*)&Ws[r][c] = *(const uint4*)(W + (size_t)r * Nout + n0 + c);
    }
    __syncthreads();

    const uint32_t offA144 = (uint32_t)(((seg & 1) * 8 + l8) * 144 + ((seg >> 1) & 1) * 16);
    const uint32_t offA272 = (uint32_t)(((seg & 1) * 8 + l8) * 272 + ((seg >> 1) & 1) * 16);
    const uint32_t asa = (uint32_t)__cvta_generic_to_shared(&As[0][0]) + offA144
                       + (uint32_t)(w * 16 * 144);
    const uint32_t wsa = (uint32_t)__cvta_generic_to_shared(&Ws[0][0]) + offA272;

    uint32_t qf[4][4];
    #pragma unroll
    for (int ks = 0; ks < 4; ks++)
        ldsm_x4(qf[ks][0], qf[ks][1], qf[ks][2], qf[ks][3],
                asa + (uint32_t)(ks * 32));

    float c4[16][4];
    #pragma unroll
    for (int n = 0; n < 16; n++)
        #pragma unroll
        for (int j = 0; j < 4; j++) c4[n][j] = 0.0f;

    #pragma unroll
    for (int ks = 0; ks < 4; ks++) {
        #pragma unroll
        for (int ntp = 0; ntp < 8; ntp++) {
            uint32_t b00, b01, b10, b11;
            ldsm_x4_t(b00, b01, b10, b11,
                      wsa + (uint32_t)(ks * 16 * 272 + ntp * 32));
            mma16816(c4[2 * ntp],     qf[ks], b00, b01);
            mma16816(c4[2 * ntp + 1], qf[ks], b10, b11);
        }
    }

    const int row0 = m0 + 16 * w + g;
    #pragma unroll
    for (int n = 0; n < 16; n++) {
        int col = n0 + 8 * n + 2 * tig;
        float v0 = c4[n][0], v1 = c4[n][1], v2 = c4[n][2], v3 = c4[n][3];
        if (bias) {
            float b0 = bias[col], b1 = bias[col + 1];
            v0 += b0; v1 += b1; v2 += b0; v3 += b1;
        }
        if (BF16OUT) {
            bf16* out = (bf16*)outv;
            *(uint32_t*)(out + (size_t)row0 * Nout + col)       = pack_bf16(v0, v1);
            *(uint32_t*)(out + (size_t)(row0 + 8) * Nout + col) = pack_bf16(v2, v3);
        } else {
            float* out = (float*)outv;
            *(float2*)(out + (size_t)row0 * Nout + col)       = make_float2(v0, v1);
            *(float2*)(out + (size_t)(row0 + 8) * Nout + col) = make_float2(v2, v3);
        }
    }
}

// ---------------------------------------------------------------------------
// Flash attention, bf16 mma.sync, fp32 accum, online softmax.
// Grid (32 q-tiles, 32 bh), 128 thr (4 warps). 2-stage cp.async K/V pipeline.
// Output attn written as bf16.
// ---------------------------------------------------------------------------
#define ROWB 144
#define KVSTAGE (64 * 144)

__global__ void __launch_bounds__(128)
flash_mma_kernel(const bf16* __restrict__ qkv, bf16* __restrict__ attn_out)
{
    __shared__ __align__(16) bf16 Qs[64][72];
    __shared__ __align__(16) bf16 Ks[2][64][72];
    __shared__ __align__(16) bf16 Vs[2][64][72];

    const int qt   = blockIdx.x;
    const int bh   = blockIdx.y;
    const int b    = bh >> 4;
    const int h    = bh & 15;
    const int tid  = threadIdx.x;
    const int w    = tid >> 5;
    const int lane = tid & 31;
    const int g    = lane >> 2;
    const int tig  = lane & 3;
    const int l8   = lane & 7;
    const int seg  = lane >> 3;

    const uint32_t offA = (uint32_t)(((seg & 1) * 8 + l8) * ROWB + ((seg >> 1) & 1) * 16);
    const uint32_t offB = (uint32_t)((((seg >> 1) & 1) * 8 + l8) * ROWB + (seg & 1) * 16);

    const uint32_t qsa = (uint32_t)__cvta_generic_to_shared(&Qs[0][0]) + offA;
    const uint32_t ksa = (uint32_t)__cvta_generic_to_shared(&Ks[0][0][0]) + offB;
    const uint32_t vsa = (uint32_t)__cvta_generic_to_shared(&Vs[0][0][0]) + offA;

    const bf16* qbase = qkv + (size_t)(b * N_ + qt * 64) * QKV3_ + h * DH_;
    const bf16* kbase = qkv + (size_t)(b * N_) * QKV3_ + C_ + h * DH_;
    const bf16* vbase = kbase + C_;

    // Load Q tile
    #pragma unroll
    for (int rep = 0; rep < 4; rep++) {
        int idx = tid + 128 * rep;
        int r = idx >> 3, c = (idx & 7) * 8;
        *(uint4*)&Qs[r][c] = *(const uint4*)(qbase + (size_t)r * QKV3_ + c);
    }

    // Prologue: stage 0 of K/V via cp.async
    #pragma unroll
    for (int rep = 0; rep < 4; rep++) {
        int idx = tid + 128 * rep;
        int r = idx >> 3, c = (idx & 7) * 8;
        size_t go = (size_t)r * QKV3_ + c;
        cp16(&Ks[0][r][c], kbase + go);
        cp16(&Vs[0][r][c], vbase + go);
    }
    asm volatile("cp.async.commit_group;");

    __syncthreads();
    uint32_t qf[4][4];
    #pragma unroll
    for (int ks = 0; ks < 4; ks++)
        ldsm_x4(qf[ks][0], qf[ks][1], qf[ks][2], qf[ks][3],
                qsa + (uint32_t)(w * 16 * ROWB + ks * 32));

    float o[8][4];
    #pragma unroll
    for (int n = 0; n < 8; n++)
        #pragma unroll
        for (int j = 0; j < 4; j++) o[n][j] = 0.0f;
    float m0 = -1e30f, m1 = -1e30f, l0 = 0.0f, l1 = 0.0f;
    const float scale = 0.125f;

    const int T = N_ / 64;
    for (int t = 0; t < T; t++) {
        if (t + 1 < T) {
            const int s = (t + 1) & 1;
            #pragma unroll
            for (int rep = 0; rep < 4; rep++) {
                int idx = tid + 128 * rep;
                int r = idx >> 3, c = (idx & 7) * 8;
                size_t go = (size_t)((t + 1) * 64 + r) * QKV3_ + c;
                cp16(&Ks[s][r][c], kbase + go);
                cp16(&Vs[s][r][c], vbase + go);
            }
            asm volatile("cp.async.commit_group;");
            asm volatile("cp.async.wait_group 1;");
        } else {
            asm volatile("cp.async.wait_group 0;");
        }
        __syncthreads();

        const uint32_t kb = ksa + (uint32_t)((t & 1) * KVSTAGE);
        const uint32_t vb = vsa + (uint32_t)((t & 1) * KVSTAGE);

        // S = Q K^T
        float s[8][4];
        #pragma unroll
        for (int n = 0; n < 8; n++)
            #pragma unroll
            for (int j = 0; j < 4; j++) s[n][j] = 0.0f;

        #pragma unroll
        for (int ks = 0; ks < 4; ks++) {
            #pragma unroll
            for (int ntp = 0; ntp < 4; ntp++) {
                uint32_t b00, b01, b10, b11;
                ldsm_x4(b00, b01, b10, b11,
                        kb + (uint32_t)(ntp * 16 * ROWB + ks * 32));
                mma16816(s[2 * ntp],     qf[ks], b00, b01);
                mma16816(s[2 * ntp + 1], qf[ks], b10, b11);
            }
        }

        // Online softmax
        float mx0 = -1e30f, mx1 = -1e30f;
        #pragma unroll
        for (int n = 0; n < 8; n++) {
            s[n][0] *= scale; s[n][1] *= scale; s[n][2] *= scale; s[n][3] *= scale;
            mx0 = fmaxf(mx0, fmaxf(s[n][0], s[n][1]));
            mx1 = fmaxf(mx1, fmaxf(s[n][2], s[n][3]));
        }
        mx0 = fmaxf(mx0, __shfl_xor_sync(0xffffffffu, mx0, 1));
        mx0 = fmaxf(mx0, __shfl_xor_sync(0xffffffffu, mx0, 2));
        mx1 = fmaxf(mx1, __shfl_xor_sync(0xffffffffu, mx1, 1));
        mx1 = fmaxf(mx1, __shfl_xor_sync(0xffffffffu, mx1, 2));

        float mn0 = fmaxf(m0, mx0), mn1 = fmaxf(m1, mx1);
        float cr0 = __expf(m0 - mn0), cr1 = __expf(m1 - mn1);
        m0 = mn0; m1 = mn1;

        float rs0 = 0.0f, rs1 = 0.0f;
        #pragma unroll
        for (int n = 0; n < 8; n++) {
            s[n][0] = __expf(s[n][0] - mn0);
            s[n][1] = __expf(s[n][1] - mn0);
            s[n][2] = __expf(s[n][2] - mn1);
            s[n][3] = __expf(s[n][3] - mn1);
            rs0 += s[n][0] + s[n][1];
            rs1 += s[n][2] + s[n][3];
        }
        rs0 += __shfl_xor_sync(0xffffffffu, rs0, 1);
        rs0 += __shfl_xor_sync(0xffffffffu, rs0, 2);
        rs1 += __shfl_xor_sync(0xffffffffu, rs1, 1);
        rs1 += __shfl_xor_sync(0xffffffffu, rs1, 2);
        l0 = l0 * cr0 + rs0;
        l1 = l1 * cr1 + rs1;
        #pragma unroll
        for (int n = 0; n < 8; n++) {
            o[n][0] *= cr0; o[n][1] *= cr0; o[n][2] *= cr1; o[n][3] *= cr1;
        }

        // O += P V
        #pragma unroll
        for (int ks = 0; ks < 4; ks++) {
            uint32_t a[4];
            a[0] = pack_bf16(s[2 * ks    ][0], s[2 * ks    ][1]);
            a[1] = pack_bf16(s[2 * ks    ][2], s[2 * ks    ][3]);
            a[2] = pack_bf16(s[2 * ks + 1][0], s[2 * ks + 1][1]);
            a[3] = pack_bf16(s[2 * ks + 1][2], s[2 * ks + 1][3]);
            #pragma unroll
            for (int ntp = 0; ntp < 4; ntp++) {
                uint32_t b00, b01, b10, b11;
                ldsm_x4_t(b00, b01, b10, b11,
                          vb + (uint32_t)(ks * 16 * ROWB + ntp * 32));
                mma16816(o[2 * ntp],     a, b00, b01);
                mma16816(o[2 * ntp + 1], a, b10, b11);
            }
        }
        __syncthreads();
    }

    // Epilogue: bf16 output
    float inv0 = 1.0f / l0, inv1 = 1.0f / l1;
    int row0 = b * N_ + qt * 64 + 16 * w + g;
    bf16* out0 = attn_out + (size_t)row0 * C_ + h * DH_;
    bf16* out1 = out0 + (size_t)8 * C_;
    #pragma unroll
    for (int n = 0; n < 8; n++) {
        *(uint32_t*)(out0 + 8 * n + 2 * tig) = pack_bf16(o[n][0] * inv0, o[n][1] * inv0);
        *(uint32_t*)(out1 + 8 * n + 2 * tig) = pack_bf16(o[n][2] * inv1, o[n][3] * inv1);
    }
}

// ---------------------------------------------------------------------------
extern "C" void kernel_launch(void* const* d_in, const int* in_sizes, int n_in,
                              void* d_out, int out_size)
{
    const float* x        = (const float*)d_in[0];
    const float* w_qkv_a  = (const float*)d_in[1];
    const float* w_qkv_b  = (const float*)d_in[2];
    const float* w_proj_a = (const float*)d_in[3];
    const float* b_proj_a = (const float*)d_in[4];
    const float* w_proj_b = (const float*)d_in[5];
    const float* b_proj_b = (const float*)d_in[6];
    float* out = (float*)d_out;

    bf16 *x_bf, *wqa, *wqb, *wpa, *wpb, *h1, *qkv, *attn, *h2;
    cudaGetSymbolAddress((void**)&x_bf, g_x_bf);
    cudaGetSymbolAddress((void**)&wqa,  g_wqa);
    cudaGetSymbolAddress((void**)&wqb,  g_wqb);
    cudaGetSymbolAddress((void**)&wpa,  g_wpa);
    cudaGetSymbolAddress((void**)&wpb,  g_wpb);
    cudaGetSymbolAddress((void**)&h1,   g_h1);
    cudaGetSymbolAddress((void**)&qkv,  g_qkv);
    cudaGetSymbolAddress((void**)&attn, g_attn);
    cudaGetSymbolAddress((void**)&h2,   g_h2);

    // 0) conversions to bf16
    cvt_kernel<<<(M_ * C_ / 4 + 255) / 256, 256>>>(x, x_bf, M_ * C_ / 4);
    cvt_kernel<<<(C_ * R_ / 4 + 255) / 256, 256>>>(w_qkv_a, wqa, C_ * R_ / 4);
    cvt_kernel<<<(R_ * QKV3_ / 4 + 255) / 256, 256>>>(w_qkv_b, wqb, R_ * QKV3_ / 4);
    cvt_kernel<<<(C_ * R_ / 4 + 255) / 256, 256>>>(w_proj_a, wpa, C_ * R_ / 4);
    cvt_kernel<<<(R_ * C_ / 4 + 255) / 256, 256>>>(w_proj_b, wpb, R_ * C_ / 4);

    // 1) h1 = gelu(x @ w_qkv_a)
    gemm_rank_tc<<<M_ / 32, 128>>>(x_bf, wqa, nullptr, h1);
    // 2) qkv = h1 @ w_qkv_b  (bf16 out)
    gemm_expand_tc<1><<<dim3(QKV3_ / 128, M_ / 64), 128>>>(h1, wqb, nullptr, qkv, QKV3_);
    // 3) attention
    flash_mma_kernel<<<dim3(N_ / 64, B_ * H_), 128>>>(qkv, attn);
    // 4) h2 = gelu(attn @ w_proj_a + b_proj_a)
    gemm_rank_tc<<<M_ / 32, 128>>>(attn, wpa, b_proj_a, h2);
    // 5) out = h2 @ w_proj_b + b_proj_b  (fp32 out)
    gemm_expand_tc<0><<<dim3(C_ / 128, M_ / 64), 128>>>(h2, wpb, b_proj_b, out, C_);
}